// round 17
// baseline (speedup 1.0000x reference)
#include <cuda_runtime.h>
#include <stdint.h>

#define BB 8
#define SS 2047
#define RT 1162
#define ROWS (BB * SS)
#define NEGF (-1e9f)
#define CH 128
#define NCH 16
#define GRID_F 888                   // 6 blocks/SM x 148 SMs -> ALL resident at t0
#define WARPS_TOTAL (GRID_F * 8)     // 7104 warps, <=3 rows each

// Chunk-LOCAL inclusive prefix per (b, j), padded to 2048 rows per batch.
// words 0..4 = instrument-present bitset (129 bits),
// word 5 = key_sign:  flag<<31 | j<<8 | value   (max selects latest; value inline)
// word 6 = time_sign: same encoding
// word 7 = tempo:     j<<8 | value, element j==0 always seeds its value
//          (matches jnp.argmax-of-zeros -> song[b,0,feat] semantics).
__device__ uint32_t g_prefix[(size_t)BB * 2048 * 8];
__device__ uint32_t g_agg[BB * NCH * 8];
__device__ int g_scan_done;   // -> 128 per launch; reset by last finishing block
__device__ int g_fin;         // completion counter; reset with g_scan_done

__constant__ int c_num[12] = {1, 2, 3, 4, 5, 6, 7, 8, 9, 10, 12, 16};

__device__ __forceinline__ uint32_t pmax(uint32_t a, uint32_t b) { return a > b ? a : b; }

// ONE kernel. Blocks 0..127 additionally perform the scan duty for one chunk
// before joining the copy. Handshake via g_scan_done (all blocks resident).
__global__ __launch_bounds__(256, 6) void fused_kernel(const int* __restrict__ song,
                                                       const int* __restrict__ chosen,
                                                       const float* __restrict__ scores,
                                                       float* __restrict__ out) {
    int tid = threadIdx.x;
    int warp = tid >> 5;
    int lane = tid & 31;
    int bid = blockIdx.x;
    int gw = bid * 8 + warp;             // 0..7103

    __shared__ int sp_all[8][16];
    __shared__ uint32_t s_carry[BB * NCH][8];   // exclusive carry table (4KB)
    __shared__ uint32_t s_agg[4][8];
    int* sp = sp_all[warp];

    // ================= scan duty (blocks 0..127, threads 0..127) =============
    if (bid < BB * NCH) {
        int b = bid >> 4;
        int c = bid & 15;
        int j = c * CH + tid;             // only tid<128 has a valid element

        uint32_t S[8] = {0, 0, 0, 0, 0, 0, 0, 0};
        if (tid < CH && j < SS) {
            const int* e = song + ((size_t)b * SS + j) * 11;
            int ty = e[0];                // all 5 loads issued together (MLP)
            int v6 = e[6];
            int v8 = e[8];
            int v9 = e[9];
            int v10 = e[10];
            if (ty == 1) {
                S[v6 >> 5] |= 1u << (v6 & 31);
            } else if (ty == 4) {
                S[5] = 0x80000000u | ((uint32_t)j << 8) | (uint32_t)v8;
            } else if (ty == 5) {
                S[6] = 0x80000000u | ((uint32_t)j << 8) | (uint32_t)v9;
            } else if (ty == 6) {
                S[7] = ((uint32_t)j << 8) | (uint32_t)v10;
            }
            if (j == 0) {   // seed: no-match default is index 0 -> its value
                S[5] = pmax(S[5], (uint32_t)v8);
                S[6] = pmax(S[6], (uint32_t)v9);
                S[7] = pmax(S[7], (uint32_t)v10);
            }
        }

#pragma unroll
        for (int d = 1; d < 32; d <<= 1) {
            uint32_t o[8];
#pragma unroll
            for (int w = 0; w < 8; ++w) o[w] = __shfl_up_sync(0xffffffffu, S[w], d);
            if (lane >= d) {
                S[0] |= o[0]; S[1] |= o[1]; S[2] |= o[2]; S[3] |= o[3]; S[4] |= o[4];
                S[5] = pmax(S[5], o[5]); S[6] = pmax(S[6], o[6]); S[7] = pmax(S[7], o[7]);
            }
        }
        if (warp < 4 && lane == 31) {
#pragma unroll
            for (int w = 0; w < 8; ++w) s_agg[warp][w] = S[w];
        }
        __syncthreads();
        if (warp < 4) {
#pragma unroll
            for (int w2 = 0; w2 < 3; ++w2) {
                if (warp > w2) {
                    S[0] |= s_agg[w2][0]; S[1] |= s_agg[w2][1]; S[2] |= s_agg[w2][2];
                    S[3] |= s_agg[w2][3]; S[4] |= s_agg[w2][4];
                    S[5] = pmax(S[5], s_agg[w2][5]);
                    S[6] = pmax(S[6], s_agg[w2][6]);
                    S[7] = pmax(S[7], s_agg[w2][7]);
                }
            }
        }

        if (tid < CH && j < SS) {
            uint4* dst = (uint4*)&g_prefix[((size_t)b * 2048 + j) * 8];
            dst[0] = make_uint4(S[0], S[1], S[2], S[3]);
            dst[1] = make_uint4(S[4], S[5], S[6], S[7]);
        }
        int lastt = (c == NCH - 1) ? (SS - 1 - c * CH) : (CH - 1);
        if (tid == lastt) {
            uint4* a = (uint4*)&g_agg[bid * 8];
            a[0] = make_uint4(S[0], S[1], S[2], S[3]);
            a[1] = make_uint4(S[4], S[5], S[6], S[7]);
        }

        // publish: stores -> barrier -> fence -> flag
        __syncthreads();
        if (tid == 0) {
            __threadfence();
            atomicAdd(&g_scan_done, 1);
        }
    }

    // ===================== phase 1: copy + argmax (no deps) ===================
    int predm[3], predb[3];
#pragma unroll
    for (int k = 0; k < 3; ++k) {
        int row = gw + k * WARPS_TOTAL;
        predm[k] = 0; predb[k] = 0;
        if (row < ROWS) {
            const float* srow = scores + (size_t)row * RT;
            float* orow = out + (size_t)row * RT;

            // measure argmax over scores[0:256] (first-index tiebreak = jnp.argmax)
            float bv = srow[lane];
            int bi = lane;
#pragma unroll
            for (int q = 1; q < 8; ++q) {
                float v = srow[lane + 32 * q];
                if (v > bv) { bv = v; bi = lane + 32 * q; }
            }
#pragma unroll
            for (int d = 16; d; d >>= 1) {
                float ov = __shfl_down_sync(0xffffffffu, bv, d);
                int oi = __shfl_down_sync(0xffffffffu, bi, d);
                if (ov > bv || (ov == bv && oi < bi)) { bv = ov; bi = oi; }
            }
            predm[k] = bi;   // valid on lane 0

            // beat argmax over scores[256:272]
            float bb = srow[256 + (lane & 15)];
            int bj = lane & 15;
#pragma unroll
            for (int d = 8; d; d >>= 1) {
                float ov = __shfl_down_sync(0xffffffffu, bb, d, 16);
                int oj = __shfl_down_sync(0xffffffffu, bj, d, 16);
                if (ov > bb || (ov == bb && oj < bj)) { bb = ov; bj = oj; }
            }
            predb[k] = bj;   // valid on lane 0

            // float4 copy (row byte offset = row*4648; 16B-aligned iff row even)
            if ((row & 1) == 0) {
                const float4* s4 = (const float4*)srow;
                float4* o4 = (float4*)orow;
                for (int p = lane; p < 290; p += 32) o4[p] = s4[p];
                if (lane == 0) *(float2*)(orow + 1160) = *(const float2*)(srow + 1160);
            } else {
                const float4* s4 = (const float4*)(srow + 2);
                float4* o4 = (float4*)(orow + 2);
                for (int p = lane; p < 290; p += 32) o4[p] = s4[p];
                if (lane == 0) *(float2*)orow = *(const float2*)srow;
            }
        }
    }

    // ============ phase 2: wait for scan publish (set ~20us ago) =============
    if (tid == 0) {
        while (*(volatile int*)&g_scan_done < BB * NCH) { }
    }
    __syncthreads();
    __threadfence();   // acquire ordering for every reading thread

    // ====== build exclusive carry table once per block (8 warps x 1 batch) ====
    {
        int wb = warp;            // warp w handles batch w
        int l16 = lane & 15;
        const uint4* AG = (const uint4*)&g_agg[(wb * NCH + l16) * 8];
        uint4 A = (lane < 16) ? AG[0] : AG[1];   // lo: words 0-3 (OR); hi: 4-7
#pragma unroll
        for (int d = 1; d < 16; d <<= 1) {
            uint4 o;
            o.x = __shfl_up_sync(0xffffffffu, A.x, d, 16);
            o.y = __shfl_up_sync(0xffffffffu, A.y, d, 16);
            o.z = __shfl_up_sync(0xffffffffu, A.z, d, 16);
            o.w = __shfl_up_sync(0xffffffffu, A.w, d, 16);
            if (l16 >= d) {
                if (lane < 16) { A.x |= o.x; A.y |= o.y; A.z |= o.z; A.w |= o.w; }
                else { A.x |= o.x; A.y = pmax(A.y, o.y); A.z = pmax(A.z, o.z); A.w = pmax(A.w, o.w); }
            }
        }
        // exclusive: shift by one entry
        uint4 E;
        E.x = __shfl_up_sync(0xffffffffu, A.x, 1, 16);
        E.y = __shfl_up_sync(0xffffffffu, A.y, 1, 16);
        E.z = __shfl_up_sync(0xffffffffu, A.z, 1, 16);
        E.w = __shfl_up_sync(0xffffffffu, A.w, 1, 16);
        if (l16 == 0) E = make_uint4(0, 0, 0, 0);
        uint32_t* dst = s_carry[wb * NCH + l16];
        if (lane < 16) {
            dst[0] = E.x; dst[1] = E.y; dst[2] = E.z; dst[3] = E.w;
        } else {
            dst[4] = E.x; dst[5] = E.y; dst[6] = E.z; dst[7] = E.w;
        }
    }
    __syncthreads();

    // ============== phase 3: params + sparse overwrites per row ==============
#pragma unroll
    for (int k = 0; k < 3; ++k) {
        int row = gw + k * WARPS_TOTAL;
        if (row >= ROWS) break;
        int b = row / SS;
        int i = row - b * SS;
        float* orow = out + (size_t)row * RT;

        if (lane == 0) {
            int jj = (i + 1 < SS) ? i + 1 : SS - 1;
            int cc = jj >> 7;
            const uint4* PL = (const uint4*)&g_prefix[((size_t)b * 2048 + jj) * 8];
            uint4 p0 = PL[0], p1 = PL[1];
            const uint32_t* CR = s_carry[b * NCH + cc];
            const int* si = song + (size_t)row * 11;
            int sm1 = si[1], sb2 = si[2], sp3 = si[3];
            int tcho = chosen[row];

            uint32_t w0 = p0.x | CR[0], w1 = p0.y | CR[1], w2 = p0.z | CR[2];
            uint32_t w3 = p0.w | CR[3], w4 = p1.x | CR[4];
            uint32_t wk = pmax(p1.y, CR[5]), wt = pmax(p1.z, CR[6]), wp = pmax(p1.w, CR[7]);

            int last_ks = (int)(wk & 0xffu);
            int last_ts = (int)(wt & 0xffu);
            int last_tp = (int)(wp & 0xffu);
            bool has_ks = (wk >> 31) != 0;
            bool has_ts = (wt >> 31) != 0;
            int max_beat = c_num[last_ts % 12];

            bool c1f = (predm[k] == sm1);
            int min_beat = c1f ? sb2 : 0;
            bool c2f = c1f && (predb[k] == min_beat);
            int min_pos = c2f ? sp3 : 0;
            int min_m46 = (sb2 == 0 && sp3 == 0) ? sm1 : sm1 + 1;
            bool has_inst = (w0 | w1 | w2 | w3 | w4) != 0;
            bool is3 = (tcho == 3);

            sp[0] = (int)w0; sp[1] = (int)w1; sp[2] = (int)w2;
            sp[3] = (int)w3; sp[4] = (int)w4;
            sp[5] = is3 ? sm1 : ((tcho >= 4 && tcho <= 6) ? min_m46 : 0);
            sp[6] = is3 ? min_beat : 0;
            sp[7] = is3 ? max_beat : 16;
            sp[8] = is3 ? min_pos : 0;
            sp[9] = is3 ? 1 : ((tcho == 1 && has_inst) ? 2 : 0);
            sp[10] = is3 ? 1 : ((tcho == 4 && has_ks) ? 2 : 0);
            sp[11] = last_ks;
            sp[12] = is3 ? 1 : ((tcho == 5 && has_ts) ? 2 : 0);
            sp[13] = last_ts;
            sp[14] = is3 ? 1 : ((tcho == 6) ? 2 : 0);
            sp[15] = last_tp;
        }
        __syncwarp();

        int mth = sp[5], blo = sp[6], bhi = sp[7], pth = sp[8];
        int imode = sp[9], kmode = sp[10], kval = sp[11];
        int tsm = sp[12], tsv = sp[13], tpm = sp[14], tpv = sp[15];

        for (int c = lane; c < mth; c += 32) orow[c] = NEGF;                 // measure
        if (lane < 16 && (lane < blo || lane >= bhi)) orow[256 + lane] = NEGF;  // beat
        for (int p = lane; p < pth; p += 32) orow[272 + p] = NEGF;           // position
        if (imode) {                                                          // instrument
#pragma unroll
            for (int q = 0; q < 5; ++q) {
                int ci = lane + 32 * q;
                if (ci < 129) {
                    bool pres = ((uint32_t)sp[q] >> lane) & 1u;
                    bool masked = (imode == 1) ? !pres : pres;
                    if (masked) orow[784 + ci] = NEGF;
                }
            }
        }
        if (kmode && lane < 24) {                                             // key_sign
            bool masked = (kmode == 1) ? (lane != kval) : (lane == kval);
            if (masked) orow[1041 + lane] = NEGF;
        }
        if (tsm) {                                                            // time_sign
#pragma unroll
            for (int q = 0; q < 2; ++q) {
                int ct = lane + 32 * q;
                if (ct < 48) {
                    bool masked = (tsm == 1) ? (ct != tsv) : (ct == tsv);
                    if (masked) orow[1065 + ct] = NEGF;
                }
            }
        }
        if (tpm) {                                                            // tempo
#pragma unroll
            for (int q = 0; q < 2; ++q) {
                int cp = lane + 32 * q;
                if (cp < 49) {
                    bool masked = (tpm == 1) ? (cp != tpv) : (cp == tpv);
                    if (masked) orow[1113 + cp] = NEGF;
                }
            }
        }
        __syncwarp();   // sp reused next k
    }

    // ============ reset handshake state for the next graph replay ============
    __syncthreads();
    if (tid == 0) {
        int old = atomicAdd(&g_fin, 1);
        if (old == GRID_F - 1) {
            atomicExch(&g_scan_done, 0);
            atomicExch(&g_fin, 0);
        }
    }
}

extern "C" void kernel_launch(void* const* d_in, const int* in_sizes, int n_in,
                              void* d_out, int out_size) {
    const int* song = (const int*)d_in[0];
    const int* chosen = (const int*)d_in[1];
    const float* scores = (const float*)d_in[2];
    float* out = (float*)d_out;

    fused_kernel<<<GRID_F, 256>>>(song, chosen, scores, out);
}